// round 16
// baseline (speedup 1.0000x reference)
#include <cuda_runtime.h>
#include <cuda_fp16.h>
#include <cstdint>
#include <cstddef>

#define BB   4
#define NN_  4096
#define HH   8
#define DD   64
#define MM   256
#define LL   16
#define BH   32
#define KERN 33
#define GSPLIT 8

#if defined(__CUDA_ARCH_FEAT_SM103_ALL) || defined(__CUDA_ARCH_FEAT_SM100_ALL)
#define HAS_TC 1
#else
#define HAS_TC 0
#endif

// ---------------- scratch -----------------------------------------------------
__device__ float g_QL[BH * MM * DD];
__device__ float g_KL[BH * MM * DD];
__device__ float g_X [BH * MM * MM];
__device__ float g_ZA[BH * MM * MM];
__device__ float g_ZB[BH * MM * MM];
__device__ float g_XZ[BH * MM * MM];
__device__ float g_T2[BH * MM * MM];
__device__ float g_T3[BH * MM * MM];
__device__ float g_S [BH * (size_t)NN_ * MM];   // attn3 P stored as __half (reinterpreted)
__device__ float g_G [BH * MM * DD];
__device__ float g_Gp[GSPLIT * BH * MM * DD];
__device__ float g_W [BH * MM * DD];
__device__ float g_OA[BH * (size_t)NN_ * DD];
__device__ float g_rsum[BH * MM];
__device__ float g_scal[2];

// ---------------- PTX helpers -------------------------------------------------
__device__ __forceinline__ uint32_t elect_one_pred() {
    uint32_t pred;
    asm volatile("{\n\t.reg .pred p;\n\telect.sync _|p, 0xFFFFFFFF;\n\tselp.b32 %0, 1, 0, p;\n\t}"
                 : "=r"(pred));
    return pred;
}
__device__ __forceinline__ uint32_t smem_to_u32(const void* p) {
    uint32_t a;
    asm("{ .reg .u64 t; cvta.to.shared.u64 t, %1; cvt.u32.u64 %0, t; }" : "=r"(a) : "l"(p));
    return a;
}
#define SMEM_SWIZZLE_128B(o) ((o) ^ (((o) >> 3) & 0x70))

static constexpr uint64_t SMEM_DESC_BASE_SW128 =
    (uint64_t(2) << 61) | (uint64_t(1) << 46) | (uint64_t(64) << 32) | (uint64_t(1) << 16);
#define MAKE_SMEM_DESC(base_addr) (SMEM_DESC_BASE_SW128 | ((uint64_t)((base_addr) >> 4) & 0x3FFF))

#define FENCE_PROXY_ASYNC_SHARED_CTA() \
    asm volatile("fence.proxy.async.shared::cta;" ::: "memory")
#define MBARRIER_INIT(a, c) \
    asm volatile("mbarrier.init.shared.b64 [%0], %1;" :: "r"((uint32_t)(a)), "r"((uint32_t)(c)) : "memory")
#define MBARRIER_INVAL(a) \
    asm volatile("mbarrier.inval.shared.b64 [%0];" :: "r"((uint32_t)(a)) : "memory")
#define MBARRIER_WAIT_PARITY(mbar_smem_addr, phase_parity) do { \
    uint32_t _mbar = (uint32_t)(mbar_smem_addr); \
    uint32_t _parity = (uint32_t)(phase_parity); \
    uint32_t _done; \
    asm volatile("{\n\t.reg .pred p;\n\t" \
        "mbarrier.try_wait.parity.acquire.cta.shared::cta.b64 p, [%1], %2;\n\t" \
        "selp.b32 %0, 1, 0, p;\n\t}" \
        : "=r"(_done) : "r"(_mbar), "r"(_parity) : "memory"); \
    if (!_done) { \
        asm volatile("{\n\t.reg .pred P1;\n\t" \
            "WAIT_LOOP_%=:\n\t" \
            "mbarrier.try_wait.parity.acquire.cta.shared::cta.b64 P1, [%0], %1, 0x989680;\n\t" \
            "@P1 bra.uni WAIT_DONE_%=;\n\t" \
            "bra.uni WAIT_LOOP_%=;\n\t" \
            "WAIT_DONE_%=:\n\t}" \
            :: "r"(_mbar), "r"(_parity) : "memory"); \
    } \
} while(0)

#if HAS_TC
#define TCGEN05_ALLOC(smem_result_addr, nCols) \
    asm volatile("tcgen05.alloc.cta_group::1.sync.aligned.shared::cta.b32 [%0], %1;" \
                 :: "r"((uint32_t)(smem_result_addr)), "r"((uint32_t)(nCols)) : "memory")
#define TCGEN05_DEALLOC(tmem_addr, nCols) \
    asm volatile("tcgen05.dealloc.cta_group::1.sync.aligned.b32 %0, %1;" \
                 :: "r"(tmem_addr), "r"((uint32_t)(nCols)))
#define TCGEN05_RELINQUISH_ALLOC_PERMIT() \
    asm volatile("tcgen05.relinquish_alloc_permit.cta_group::1.sync.aligned;")
#define TCGEN05_COMMIT(mbar_smem_addr) \
    asm volatile("tcgen05.commit.cta_group::1.mbarrier::arrive::one.shared::cluster.b64 [%0];" \
                 :: "r"((uint32_t)(mbar_smem_addr)) : "memory")
#define TCGEN05_FENCE_AFTER() \
    asm volatile("tcgen05.fence::after_thread_sync;" ::: "memory")
#define TCGEN05_WAIT_LD() \
    asm volatile("tcgen05.wait::ld.sync.aligned;" ::: "memory")
#define TCGEN05_LD_32X32B_X32(r, tmem_addr) \
    asm volatile("tcgen05.ld.sync.aligned.32x32b.x32.b32 " \
        "{%0, %1, %2, %3, %4, %5, %6, %7, %8, %9, %10, %11, %12, %13, %14, %15, " \
        " %16, %17, %18, %19, %20, %21, %22, %23, %24, %25, %26, %27, %28, %29, %30, %31}, [%32];" \
        : "=r"((r)[0]),  "=r"((r)[1]),  "=r"((r)[2]),  "=r"((r)[3]), \
          "=r"((r)[4]),  "=r"((r)[5]),  "=r"((r)[6]),  "=r"((r)[7]), \
          "=r"((r)[8]),  "=r"((r)[9]),  "=r"((r)[10]), "=r"((r)[11]), \
          "=r"((r)[12]), "=r"((r)[13]), "=r"((r)[14]), "=r"((r)[15]), \
          "=r"((r)[16]), "=r"((r)[17]), "=r"((r)[18]), "=r"((r)[19]), \
          "=r"((r)[20]), "=r"((r)[21]), "=r"((r)[22]), "=r"((r)[23]), \
          "=r"((r)[24]), "=r"((r)[25]), "=r"((r)[26]), "=r"((r)[27]), \
          "=r"((r)[28]), "=r"((r)[29]), "=r"((r)[30]), "=r"((r)[31]) \
        : "r"(tmem_addr))

__device__ __forceinline__ void mma_tf32_ss(uint32_t d, uint64_t a, uint64_t b,
                                            uint32_t idesc, uint32_t en) {
    asm volatile("{\n\t.reg .pred p;\n\tsetp.ne.u32 p, %4, 0;\n\t"
                 "tcgen05.mma.cta_group::1.kind::tf32 [%0], %1, %2, %3, p;\n\t}"
                 :: "r"(d), "l"(a), "l"(b), "r"(idesc), "r"(en) : "memory");
}
#endif // HAS_TC

// ---------------- landmarks (also zeroes g_scal) ------------------------------
__global__ void landmarks_k(const float* __restrict__ q, const float* __restrict__ k)
{
    int bh = blockIdx.y, i = blockIdx.x, d = threadIdx.x;
    if (bh == 0 && i == 0 && d < 2) g_scal[d] = 0.f;
    int b = bh >> 3, h = bh & 7;
    float sq = 0.f, sk = 0.f;
    #pragma unroll
    for (int j = 0; j < LL; j++) {
        size_t idx = (((size_t)b * NN_ + (size_t)i * LL + j) * HH + h) * DD + d;
        sq += q[idx];
        sk += k[idx];
    }
    size_t o = ((size_t)bh * MM + i) * DD + d;
    g_QL[o] = sq * (0.125f / (float)LL);
    g_KL[o] = sk * (1.0f  / (float)LL);
}

// ---------------- tcgen05 tf32 batched GEMM (2-stage pipelined, 256 thr) ------
// C = alpha * (A @ B^T) + beta * E.
// EXPSUM: C = exp(that) stored as __half (buffer reinterpreted), fp32 row sums
//   atomically accumulated into Rsum[bh*MM + m].
// AHALF:  A operand read as __half, converted to fp32 in the SMEM loader
//   (only instantiated with KC=32).
template<int NT, int KC, bool TRANSB, bool EXPSUM, bool AHALF>
__global__ void __launch_bounds__(256)
tcgemm_k(const float* __restrict__ A, size_t a_so, size_t a_si, int lda,
         const float* __restrict__ B, size_t b_so, size_t b_si, int ldb,
         float* __restrict__ C, size_t c_so, size_t c_si, int ldc,
         const float* __restrict__ E, size_t e_so, size_t e_si, int lde,
         float* __restrict__ Rsum,
         int K, int nsplit, size_t c_split, float alpha, float beta)
{
#if HAS_TC
    constexpr int NJ   = KC / 32;
    constexpr int ASZ  = 128 * KC * 4;
    constexpr int BSZ  = NT * KC * 4;
    constexpr int F4R  = KC / 4;
    constexpr int F8R  = KC / 8;

    extern __shared__ char dsm[];
    uint32_t base  = smem_to_u32(dsm);
    uint32_t abase0 = (base + 1023u) & ~1023u;
    uint32_t abase1 = abase0 + ASZ;
    uint32_t bbase0 = abase1 + ASZ;
    uint32_t bbase1 = bbase0 + BSZ;
    uint32_t aux    = bbase1 + BSZ;
    char* dA01[2] = { dsm + (abase0 - base), dsm + (abase1 - base) };
    char* dB01[2] = { dsm + (bbase0 - base), dsm + (bbase1 - base) };
    uint32_t tptr_addr = aux;
    uint32_t mbar0 = aux + 8;
    uint32_t mbar1 = aux + 16;

    int t = threadIdx.x, wid = t >> 5;
    int z = blockIdx.z, bh = z / nsplit, s = z - bh * nsplit;
    int b = bh >> 3, h = bh & 7;
    const size_t a_off = (size_t)b * a_so + (size_t)h * a_si;
    const size_t c_off = (size_t)b * c_so + (size_t)h * c_si + (size_t)s * c_split;
    const float*  Af = A + a_off;
    const __half* Ah = (const __half*)A + a_off;
    float*  Cf = C + c_off;
    __half* Ch = (__half*)C + c_off;
    B += (size_t)b * b_so + (size_t)h * b_si;
    if (E) E += (size_t)b * e_so + (size_t)h * e_si;

    const int m0 = blockIdx.y * 128;
    const int n0 = blockIdx.x * NT;
    const int Kper = K / nsplit;
    const int kb0 = s * Kper;
    const int nchunk = Kper / KC;

    if (wid == 0) TCGEN05_ALLOC(tptr_addr, NT);
    if (t == 0) { MBARRIER_INIT(mbar0, 1); MBARRIER_INIT(mbar1, 1); }
    __syncthreads();
    uint32_t tmem;
    asm volatile("ld.shared.b32 %0, [%1];" : "=r"(tmem) : "r"(tptr_addr));
    if (wid == 0) TCGEN05_RELINQUISH_ALLOC_PERMIT();

    const uint32_t idesc = (1u << 4) | (2u << 7) | (2u << 10) |
                           ((uint32_t)(NT / 8) << 17) | (8u << 24);
    const uint64_t adesc[2] = { MAKE_SMEM_DESC(abase0), MAKE_SMEM_DESC(abase1) };
    const uint64_t bdesc[2] = { MAKE_SMEM_DESC(bbase0), MAKE_SMEM_DESC(bbase1) };

    int ph0 = 0, ph1 = 0;
    for (int c = 0; c < nchunk; c++) {
        const int st = c & 1;
        if (c >= 2) {
            if (st) { MBARRIER_WAIT_PARITY(mbar1, ph1); ph1 ^= 1; }
            else    { MBARRIER_WAIT_PARITY(mbar0, ph0); ph0 ^= 1; }
        }
        char* dA = dA01[st];
        char* dB = dB01[st];
        const int kb = kb0 + c * KC;
        if (!AHALF) {
            #pragma unroll
            for (int p = 0; p < (128 * F4R) / 256; p++) {
                int idx = t + p * 256;
                int r = idx / F4R, f = idx % F4R;
                int j = f >> 3, fj = f & 7;
                float4 v4 = *(const float4*)(Af + (size_t)(m0 + r) * lda + kb + f * 4);
                *(float4*)(dA + j * 16384 + SMEM_SWIZZLE_128B((uint32_t)(r * 128 + fj * 16))) = v4;
            }
        } else {
            // half A loader (KC=32 only): 8 halves per 16B load -> 2 float4 stores
            #pragma unroll
            for (int p = 0; p < (128 * F8R) / 256; p++) {
                int idx = t + p * 256;
                int r = idx / F8R, g = idx % F8R;
                uint4 hv = *(const uint4*)(Ah + (size_t)(m0 + r) * lda + kb + g * 8);
                const __half2* hp = (const __half2*)&hv;
                float2 f0 = __half22float2(hp[0]);
                float2 f1 = __half22float2(hp[1]);
                float2 f2 = __half22float2(hp[2]);
                float2 f3 = __half22float2(hp[3]);
                uint32_t off = (uint32_t)(r * 128 + g * 32);
                *(float4*)(dA + SMEM_SWIZZLE_128B(off))      = make_float4(f0.x, f0.y, f1.x, f1.y);
                *(float4*)(dA + SMEM_SWIZZLE_128B(off + 16)) = make_float4(f2.x, f2.y, f3.x, f3.y);
            }
        }
        if (!TRANSB) {
            #pragma unroll
            for (int p = 0; p < (NT * F4R) / 256; p++) {
                int idx = t + p * 256;
                int r = idx / F4R, f = idx % F4R;
                int j = f >> 3, fj = f & 7;
                float4 v4 = *(const float4*)(B + (size_t)(n0 + r) * ldb + kb + f * 4);
                *(float4*)(dB + j * (NT * 128) + SMEM_SWIZZLE_128B((uint32_t)(r * 128 + fj * 16))) = v4;
            }
        } else {
            constexpr int NF = NT / 4;
            #pragma unroll
            for (int p = 0; p < (KC * NF) / 256; p++) {
                int idx = t + p * 256;
                int kk = idx / NF, nf = idx - kk * NF;
                int j = kk >> 5, kkin = kk & 31;
                float4 v4 = *(const float4*)(B + (size_t)(kb + kk) * ldb + n0 + nf * 4);
                int nb = nf * 4;
                char* db = dB + j * (NT * 128);
                *(float*)(db + SMEM_SWIZZLE_128B((uint32_t)((nb + 0) * 128 + kkin * 4))) = v4.x;
                *(float*)(db + SMEM_SWIZZLE_128B((uint32_t)((nb + 1) * 128 + kkin * 4))) = v4.y;
                *(float*)(db + SMEM_SWIZZLE_128B((uint32_t)((nb + 2) * 128 + kkin * 4))) = v4.z;
                *(float*)(db + SMEM_SWIZZLE_128B((uint32_t)((nb + 3) * 128 + kkin * 4))) = v4.w;
            }
        }
        FENCE_PROXY_ASYNC_SHARED_CTA();
        __syncthreads();
        if (wid == 0) {
            if (elect_one_pred()) {
                #pragma unroll
                for (int j = 0; j < NJ; j++)
                    #pragma unroll
                    for (int ss = 0; ss < 4; ss++)
                        mma_tf32_ss(tmem, adesc[st] + j * 1024 + ss * 2,
                                    bdesc[st] + j * (NT * 8) + ss * 2, idesc,
                                    (c > 0 || j > 0 || ss > 0) ? 1u : 0u);
                TCGEN05_COMMIT(st ? mbar1 : mbar0);
            }
        }
    }
    if ((nchunk - 1) & 1) { MBARRIER_WAIT_PARITY(mbar1, ph1); }
    else                  { MBARRIER_WAIT_PARITY(mbar0, ph0); }

    TCGEN05_FENCE_AFTER();
    const int lid = t & 31;
    const int m = m0 + (wid & 3) * 32 + lid;
    const int half = wid >> 2;
    float lsum = 0.f;
    #pragma unroll
    for (int cb = half * (NT / 2); cb < (half + 1) * (NT / 2); cb += 32) {
        uint32_t r[32];
        TCGEN05_LD_32X32B_X32(r, tmem + cb);
        TCGEN05_WAIT_LD();
        const float* erow = E ? (E + (size_t)m * lde + (n0 + cb)) : (const float*)0;
        #pragma unroll
        for (int j = 0; j < 32; j += 4) {
            float4 o;
            o.x = alpha * __uint_as_float(r[j + 0]);
            o.y = alpha * __uint_as_float(r[j + 1]);
            o.z = alpha * __uint_as_float(r[j + 2]);
            o.w = alpha * __uint_as_float(r[j + 3]);
            if (erow) {
                float4 e4 = *(const float4*)(erow + j);
                o.x += beta * e4.x; o.y += beta * e4.y;
                o.z += beta * e4.z; o.w += beta * e4.w;
            }
            if (EXPSUM) {
                o.x = __expf(o.x); o.y = __expf(o.y);
                o.z = __expf(o.z); o.w = __expf(o.w);
                lsum += (o.x + o.y) + (o.z + o.w);
                __half* ch = Ch + (size_t)m * ldc + (n0 + cb) + j;
                *(__half2*)(ch + 0) = __floats2half2_rn(o.x, o.y);
                *(__half2*)(ch + 2) = __floats2half2_rn(o.z, o.w);
            } else {
                *(float4*)(Cf + (size_t)m * ldc + (n0 + cb) + j) = o;
            }
        }
    }
    if (EXPSUM) atomicAdd(Rsum + (size_t)bh * MM + m, lsum);
    __syncthreads();
    if (t == 0) { MBARRIER_INVAL(mbar0); MBARRIER_INVAL(mbar1); }
    __syncthreads();
    if (wid == 0) TCGEN05_DEALLOC(tmem, NT);
#else
    __trap();
#endif
}

// ---------------- fused attn1 softmax + OA GEMM (no max pass, no aliasing) ----
__global__ void __launch_bounds__(128)
fused_attn1_k(const float* __restrict__ q)
{
#if HAS_TC
    extern __shared__ char dsm[];
    uint32_t base  = smem_to_u32(dsm);
    uint32_t a0 = (base + 1023u) & ~1023u;
    uint32_t a1 = a0 + 16384;
    uint32_t b0 = a1 + 16384;
    uint32_t b1 = b0 + 32768;
    uint32_t wb = b1 + 32768;
    uint32_t p0 = wb + 65536;
    uint32_t p1 = p0 + 16384;
    uint32_t aux = p1 + 16384;
    char* dA[2] = { dsm + (a0 - base), dsm + (a1 - base) };
    char* dB[2] = { dsm + (b0 - base), dsm + (b1 - base) };
    char* dW    = dsm + (wb - base);
    char* dP[2] = { dsm + (p0 - base), dsm + (p1 - base) };
    uint32_t tptr = aux, sbar = aux + 8, pm0 = aux + 16, pm1 = aux + 24;

    const int t = threadIdx.x, wid = t >> 5, lid = t & 31;
    const int bh = blockIdx.y, b = bh >> 3, h = bh & 7;
    const int m0 = blockIdx.x * 128;
    const float* qb = q + (size_t)b * ((size_t)NN_ * HH * DD) + (size_t)h * DD;
    const float* KLb = g_KL + (size_t)bh * MM * DD;
    const float* Wb  = g_W  + (size_t)bh * MM * DD;
    float* OAb = g_OA + (size_t)bh * NN_ * DD;

    if (wid == 0) TCGEN05_ALLOC(tptr, 512);
    if (t == 0) { MBARRIER_INIT(sbar, 1); MBARRIER_INIT(pm0, 1); MBARRIER_INIT(pm1, 1); }
    __syncthreads();
    uint32_t tmem;
    asm volatile("ld.shared.b32 %0, [%1];" : "=r"(tmem) : "r"(tptr));
    if (wid == 0) TCGEN05_RELINQUISH_ALLOC_PERMIT();
    const uint32_t D1 = tmem + 256;

    #pragma unroll
    for (int kc = 0; kc < 2; kc++) {
        #pragma unroll
        for (int p = 0; p < 8; p++) {
            int idx = t + p * 128;
            int r = idx >> 3, f = idx & 7;
            float4 v4 = *(const float4*)(qb + (size_t)(m0 + r) * (HH * DD) + kc * 32 + f * 4);
            *(float4*)(dA[kc] + SMEM_SWIZZLE_128B((uint32_t)(r * 128 + f * 16))) = v4;
        }
        #pragma unroll
        for (int p = 0; p < 16; p++) {
            int idx = t + p * 128;
            int r = idx >> 3, f = idx & 7;
            float4 v4 = *(const float4*)(KLb + (size_t)r * DD + kc * 32 + f * 4);
            *(float4*)(dB[kc] + SMEM_SWIZZLE_128B((uint32_t)(r * 128 + f * 16))) = v4;
        }
    }
    #pragma unroll
    for (int cb = 0; cb < 8; cb++) {
        #pragma unroll
        for (int p = 0; p < 4; p++) {
            int idx = t + p * 128;
            int kk = idx >> 4, nf = idx & 15;
            float4 v4 = *(const float4*)(Wb + (size_t)(cb * 32 + kk) * DD + nf * 4);
            int nb = nf * 4;
            char* wchunk = dW + cb * 8192;
            *(float*)(wchunk + SMEM_SWIZZLE_128B((uint32_t)((nb + 0) * 128 + kk * 4))) = v4.x;
            *(float*)(wchunk + SMEM_SWIZZLE_128B((uint32_t)((nb + 1) * 128 + kk * 4))) = v4.y;
            *(float*)(wchunk + SMEM_SWIZZLE_128B((uint32_t)((nb + 2) * 128 + kk * 4))) = v4.z;
            *(float*)(wchunk + SMEM_SWIZZLE_128B((uint32_t)((nb + 3) * 128 + kk * 4))) = v4.w;
        }
    }
    FENCE_PROXY_ASYNC_SHARED_CTA();
    __syncthreads();

    const uint32_t idesc_s  = (1u << 4) | (2u << 7) | (2u << 10) | (32u << 17) | (8u << 24);
    const uint32_t idesc_oa = (1u << 4) | (2u << 7) | (2u << 10) | (8u  << 17) | (8u << 24);
    if (wid == 0) {
        if (elect_one_pred()) {
            #pragma unroll
            for (int kc = 0; kc < 2; kc++) {
                uint64_t ad = MAKE_SMEM_DESC(kc ? a1 : a0);
                uint64_t bdd = MAKE_SMEM_DESC(kc ? b1 : b0);
                #pragma unroll
                for (int ss = 0; ss < 4; ss++)
                    mma_tf32_ss(tmem, ad + ss * 2, bdd + ss * 2, idesc_s,
                                (kc > 0 || ss > 0) ? 1u : 0u);
            }
            TCGEN05_COMMIT(sbar);
        }
    }
    MBARRIER_WAIT_PARITY(sbar, 0);
    TCGEN05_FENCE_AFTER();

    const int prow = wid * 32 + lid;
    float sum = 0.f;
    int php0 = 0, php1 = 0;
    const uint64_t pdesc[2] = { MAKE_SMEM_DESC(p0), MAKE_SMEM_DESC(p1) };
    const uint64_t wdesc0 = MAKE_SMEM_DESC(wb);
    for (int cb = 0; cb < 8; cb++) {
        const int st = cb & 1;
        if (cb >= 2) {
            if (st) { MBARRIER_WAIT_PARITY(pm1, php1); php1 ^= 1; }
            else    { MBARRIER_WAIT_PARITY(pm0, php0); php0 ^= 1; }
        }
        uint32_t r[32];
        TCGEN05_LD_32X32B_X32(r, tmem + cb * 32);
        TCGEN05_WAIT_LD();
        float e[32];
        #pragma unroll
        for (int j = 0; j < 32; j++) {
            e[j] = __expf(0.125f * __uint_as_float(r[j]));
            sum += e[j];
        }
        char* P = dP[st];
        #pragma unroll
        for (int g = 0; g < 8; g++) {
            float4 v4 = make_float4(e[g*4], e[g*4+1], e[g*4+2], e[g*4+3]);
            *(float4*)(P + SMEM_SWIZZLE_128B((uint32_t)(prow * 128 + g * 16))) = v4;
        }
        FENCE_PROXY_ASYNC_SHARED_CTA();
        __syncthreads();
        if (wid == 0) {
            if (elect_one_pred()) {
                #pragma unroll
                for (int ss = 0; ss < 4; ss++)
                    mma_tf32_ss(D1, pdesc[st] + ss * 2, wdesc0 + cb * 512 + ss * 2,
                                idesc_oa, (cb > 0 || ss > 0) ? 1u : 0u);
                TCGEN05_COMMIT(st ? pm1 : pm0);
            }
        }
    }
    MBARRIER_WAIT_PARITY(pm1, php1);
    TCGEN05_FENCE_AFTER();

    const float inv = 1.0f / sum;
    float* orow = OAb + (size_t)(m0 + prow) * DD;
    #pragma unroll
    for (int cb = 0; cb < 2; cb++) {
        uint32_t r[32];
        TCGEN05_LD_32X32B_X32(r, D1 + cb * 32);
        TCGEN05_WAIT_LD();
        #pragma unroll
        for (int j = 0; j < 32; j += 4) {
            float4 o;
            o.x = inv * __uint_as_float(r[j + 0]);
            o.y = inv * __uint_as_float(r[j + 1]);
            o.z = inv * __uint_as_float(r[j + 2]);
            o.w = inv * __uint_as_float(r[j + 3]);
            *(float4*)(orow + cb * 32 + j) = o;
        }
    }
    __syncthreads();
    if (t == 0) { MBARRIER_INVAL(sbar); MBARRIER_INVAL(pm0); MBARRIER_INVAL(pm1); }
    __syncthreads();
    if (wid == 0) TCGEN05_DEALLOC(tmem, 512);
#else
    __trap();
#endif
}

// ---------------- register-resident row softmax (attn2 only) ------------------
template<int C>
__global__ void softmax_reg_k(float* __restrict__ X)
{
    constexpr int V = C / 256;
    float* row = X + (size_t)blockIdx.x * C;
    int t = threadIdx.x;
    float v[V];
    float mx = -1e30f;
    #pragma unroll
    for (int i = 0; i < V; i++) { v[i] = row[t + i * 256]; mx = fmaxf(mx, v[i]); }
    __shared__ float red[256];
    red[t] = mx; __syncthreads();
    for (int s = 128; s > 0; s >>= 1) { if (t < s) red[t] = fmaxf(red[t], red[t + s]); __syncthreads(); }
    mx = red[0]; __syncthreads();
    float sum = 0.f;
    #pragma unroll
    for (int i = 0; i < V; i++) { v[i] = __expf(v[i] - mx); sum += v[i]; }
    red[t] = sum; __syncthreads();
    for (int s = 128; s > 0; s >>= 1) { if (t < s) red[t] += red[t + s]; __syncthreads(); }
    float inv = 1.0f / red[0];
    #pragma unroll
    for (int i = 0; i < V; i++) row[t + i * 256] = v[i] * inv;
}

// ---------------- pinv init ---------------------------------------------------
__global__ void __launch_bounds__(1024) colmax_k(const float* __restrict__ X)
{
    int bh = blockIdx.x, t = threadIdx.x;
    int col = t & 255, part = t >> 8;
    const float* xb = X + (size_t)bh * MM * MM;
    float cs = 0.f;
    #pragma unroll 8
    for (int i = part * 64; i < part * 64 + 64; i++) cs += xb[(size_t)i * MM + col];
    __shared__ float sm[1024];
    sm[t] = cs; __syncthreads();
    if (t < 256) sm[t] = (sm[t] + sm[t + 256]) + (sm[t + 512] + sm[t + 768]);
    __syncthreads();
    for (int s = 128; s > 0; s >>= 1) {
        if (t < s) sm[t] = fmaxf(sm[t], sm[t + s]);
        __syncthreads();
    }
    if (t == 0) atomicMax((int*)&g_scal[0], __float_as_int(sm[0]));
}

__global__ void z0_k(const float* __restrict__ X, float* __restrict__ Z)
{
    __shared__ float tile[32][33];
    int bh = blockIdx.z;
    const float* xb = X + (size_t)bh * MM * MM;
    float* zb = Z + (size_t)bh * MM * MM;
    int i0 = blockIdx.x * 32, j0 = blockIdx.y * 32;
    tile[threadIdx.y][threadIdx.x] = xb[(size_t)(j0 + threadIdx.y) * MM + (i0 + threadIdx.x)];
    __syncthreads();
    float inv = 1.0f / g_scal[0];
    zb[(size_t)(i0 + threadIdx.y) * MM + (j0 + threadIdx.x)] = tile[threadIdx.x][threadIdx.y] * inv;
}

// ---------------- K-split reduce for G + softmax normalization ----------------
__global__ void reduce_g_k(const float* __restrict__ Gp, float* __restrict__ G)
{
    int i = blockIdx.x * 256 + threadIdx.x;
    const size_t stride = (size_t)BH * MM * DD;
    float s = 0.f;
    #pragma unroll
    for (int p = 0; p < GSPLIT; p++) s += Gp[(size_t)p * stride + i];
    G[i] = s / g_rsum[i >> 6];
}

// ---------------- epilogue: depthwise conv + residual + transpose ------------
__global__ void epilogue_k(const float* __restrict__ v, const float* __restrict__ rw,
                           const float* __restrict__ OA, float* __restrict__ out)
{
    __shared__ float vt[96 * 64];
    __shared__ float w[KERN];
    int bh = blockIdx.y, b = bh >> 3, h = bh & 7;
    int i0 = blockIdx.x * 64;
    int t = threadIdx.x;
    if (t < KERN) w[t] = rw[h * KERN + t];
    #pragma unroll
    for (int p = 0; p < 6; p++) {
        int idx = t + p * 256;
        int r = idx >> 4, f = idx & 15;
        int ii = i0 - 16 + r;
        float4 val = make_float4(0.f, 0.f, 0.f, 0.f);
        if (ii >= 0 && ii < NN_)
            val = *(const float4*)(v + (((size_t)b * NN_ + ii) * HH + h) * DD + f * 4);
        *(float4*)(vt + r * 64 + f * 4) = val;
    }
    __syncthreads();
    int d4 = (t & 15) * 4;
    int irow = t >> 4;
    #pragma unroll
    for (int rr = 0; rr < 4; rr++) {
        int il = irow + rr * 16;
        int i = i0 + il;
        float4 acc = *(const float4*)(OA + ((size_t)bh * NN_ + i) * DD + d4);
        #pragma unroll
        for (int tap = 0; tap < KERN; tap++) {
            float4 vv = *(const float4*)(vt + (il + tap) * 64 + d4);
            float wt = w[tap];
            acc.x += vv.x * wt; acc.y += vv.y * wt;
            acc.z += vv.z * wt; acc.w += vv.w * wt;
        }
        *(float4*)(out + (((size_t)b * NN_ + i) * HH + h) * DD + d4) = acc;
    }
}

// ---------------- host side ---------------------------------------------------
static size_t shm_gemm(int NT, int KC) {
    return 1024 + 2 * (size_t)(128 * KC * 4) + 2 * (size_t)(NT * KC * 4) + 64;
}
static const size_t SHM_FUSED = 1024 + 2 * 16384 + 2 * 32768 + 65536 + 2 * 16384 + 64;

extern "C" void kernel_launch(void* const* d_in, const int* in_sizes, int n_in,
                              void* d_out, int out_size)
{
    const float* q  = (const float*)d_in[0];
    const float* k  = (const float*)d_in[1];
    const float* v  = (const float*)d_in[2];
    const float* rw = (const float*)d_in[3];
    float* out = (float*)d_out;

    static bool attrs_set = false;
    if (!attrs_set) {
        cudaFuncSetAttribute(tcgemm_k<128, 64, true,  false, false>, cudaFuncAttributeMaxDynamicSharedMemorySize, (int)shm_gemm(128, 64));
        cudaFuncSetAttribute(tcgemm_k<128, 32, false, false, false>, cudaFuncAttributeMaxDynamicSharedMemorySize, (int)shm_gemm(128, 32));
        cudaFuncSetAttribute(tcgemm_k<128, 32, false, true,  false>, cudaFuncAttributeMaxDynamicSharedMemorySize, (int)shm_gemm(128, 32));
        cudaFuncSetAttribute(tcgemm_k<64,  32, true,  false, true >, cudaFuncAttributeMaxDynamicSharedMemorySize, (int)shm_gemm(64, 32));
        cudaFuncSetAttribute(tcgemm_k<64,  64, true,  false, false>, cudaFuncAttributeMaxDynamicSharedMemorySize, (int)shm_gemm(64, 64));
        cudaFuncSetAttribute(fused_attn1_k, cudaFuncAttributeMaxDynamicSharedMemorySize, (int)SHM_FUSED);
        attrs_set = true;
    }

    float *QL, *KL, *X, *ZA, *ZB, *XZ, *T2, *T3, *S, *G, *Gp, *W, *OA, *RS;
    cudaGetSymbolAddress((void**)&QL, g_QL);
    cudaGetSymbolAddress((void**)&KL, g_KL);
    cudaGetSymbolAddress((void**)&X,  g_X);
    cudaGetSymbolAddress((void**)&ZA, g_ZA);
    cudaGetSymbolAddress((void**)&ZB, g_ZB);
    cudaGetSymbolAddress((void**)&XZ, g_XZ);
    cudaGetSymbolAddress((void**)&T2, g_T2);
    cudaGetSymbolAddress((void**)&T3, g_T3);
    cudaGetSymbolAddress((void**)&S,  g_S);
    cudaGetSymbolAddress((void**)&G,  g_G);
    cudaGetSymbolAddress((void**)&Gp, g_Gp);
    cudaGetSymbolAddress((void**)&W,  g_W);
    cudaGetSymbolAddress((void**)&OA, g_OA);
    cudaGetSymbolAddress((void**)&RS, g_rsum);

    const size_t LB  = (size_t)MM * DD;
    const size_t XB  = (size_t)MM * MM;
    const size_t SB  = (size_t)NN_ * MM;
    const size_t QSO = (size_t)NN_ * HH * DD;
    const size_t QSI = DD;
    const int    QLD = HH * DD;

    // 0: landmarks (zeroes g_scal); rsum zeroed async
    landmarks_k<<<dim3(MM, BH), DD>>>(q, k);
    cudaMemsetAsync(RS, 0, BH * MM * sizeof(float));

    // 1: attn2 scores X = QL @ KL^T
    tcgemm_k<128, 32, false, false, false><<<dim3(2, 2, BH), 256, shm_gemm(128, 32)>>>(
        QL, 8*LB, LB, DD,  KL, 8*LB, LB, DD,  X, 8*XB, XB, MM,
        nullptr, 0, 0, 0,  nullptr,  DD, 1, 0, 1.0f, 0.0f);
    // 2: softmax rows
    softmax_reg_k<MM><<<BH * MM, 256>>>(X);
    // 3: column-sum max
    colmax_k<<<BH, 1024>>>(X);
    // 4: z0 = X^T * inv
    z0_k<<<dim3(MM/32, MM/32, BH), dim3(32, 32)>>>(X, ZA);

    // 5..28: Newton-Schulz (KC=64)
    for (int it = 0; it < 6; it++) {
        float* zc = (it & 1) ? ZB : ZA;
        float* zn = (it & 1) ? ZA : ZB;
        tcgemm_k<128, 64, true, false, false><<<dim3(2, 2, BH), 256, shm_gemm(128, 64)>>>(
            X,  8*XB, XB, MM,  zc, 8*XB, XB, MM,  XZ, 8*XB, XB, MM,
            nullptr, 0, 0, 0,  nullptr,  MM, 1, 0, 1.0f, 0.0f);
        tcgemm_k<128, 64, true, false, false><<<dim3(2, 2, BH), 256, shm_gemm(128, 64)>>>(
            XZ, 8*XB, XB, MM,  XZ, 8*XB, XB, MM,  T2, 8*XB, XB, MM,
            XZ, 8*XB, XB, MM,  nullptr,  MM, 1, 0, -1.0f, 7.0f);
        tcgemm_k<128, 64, true, false, false><<<dim3(2, 2, BH), 256, shm_gemm(128, 64)>>>(
            XZ, 8*XB, XB, MM,  T2, 8*XB, XB, MM,  T3, 8*XB, XB, MM,
            XZ, 8*XB, XB, MM,  nullptr,  MM, 1, 0, -1.0f, 15.0f);
        tcgemm_k<128, 64, true, false, false><<<dim3(2, 2, BH), 256, shm_gemm(128, 64)>>>(
            zc, 8*XB, XB, MM,  T3, 8*XB, XB, MM,  zn, 8*XB, XB, MM,
            zc, 8*XB, XB, MM,  nullptr,  MM, 1, 0, -0.25f, 3.25f);
    }
    // final z in ZA

    // attn3: S = exp(QL @ k^T) stored fp16, fp32 row sums into g_rsum
    tcgemm_k<128, 32, false, true, false><<<dim3(NN_/128, 2, BH), 256, shm_gemm(128, 32)>>>(
        QL, 8*LB, LB, DD,  k, QSO, QSI, QLD,  S, 8*SB, SB, NN_,
        nullptr, 0, 0, 0,  RS,  DD, 1, 0, 1.0f, 0.0f);

    // G = (S @ v) / rsum  (A operand read as fp16)
    tcgemm_k<64, 32, true, false, true><<<dim3(1, 2, BH * GSPLIT), 256, shm_gemm(64, 32)>>>(
        S, 8*SB, SB, NN_,  v, QSO, QSI, QLD,  Gp, 8*LB, LB, DD,
        nullptr, 0, 0, 0,  nullptr,  NN_, GSPLIT, (size_t)BH * LB, 1.0f, 0.0f);
    reduce_g_k<<<(BH * MM * DD) / 256, 256>>>(Gp, G);

    // W = ZA @ G  (KC=64)
    tcgemm_k<64, 64, true, false, false><<<dim3(1, 2, BH), 256, shm_gemm(64, 64)>>>(
        ZA, 8*XB, XB, MM,  G, 8*LB, LB, DD,  W, 8*LB, LB, DD,
        nullptr, 0, 0, 0,  nullptr,  MM, 1, 0, 1.0f, 0.0f);

    // fused attn1 softmax + OA
    fused_attn1_k<<<dim3(NN_ / 128, BH), 128, SHM_FUSED>>>(q);

    // depthwise conv residual + transpose
    epilogue_k<<<dim3(NN_ / 64, BH), 256>>>(v, rw, OA, out);
}

// round 17
// speedup vs baseline: 1.0561x; 1.0561x over previous
#include <cuda_runtime.h>
#include <cstdint>
#include <cstddef>

#define BB   4
#define NN_  4096
#define HH   8
#define DD   64
#define MM   256
#define LL   16
#define BH   32
#define KERN 33
#define GSPLIT 8

#if defined(__CUDA_ARCH_FEAT_SM103_ALL) || defined(__CUDA_ARCH_FEAT_SM100_ALL)
#define HAS_TC 1
#else
#define HAS_TC 0
#endif

// ---------------- scratch -----------------------------------------------------
__device__ float g_QL[BH * MM * DD];
__device__ float g_KL[BH * MM * DD];
__device__ float g_X [BH * MM * MM];
__device__ float g_ZA[BH * MM * MM];
__device__ float g_ZB[BH * MM * MM];
__device__ float g_XZ[BH * MM * MM];
__device__ float g_T2[BH * MM * MM];
__device__ float g_T3[BH * MM * MM];
__device__ float g_S [BH * (size_t)NN_ * MM];
__device__ float g_G [BH * MM * DD];
__device__ float g_Gp[GSPLIT * BH * MM * DD];
__device__ float g_W [BH * MM * DD];
__device__ float g_OA[BH * (size_t)NN_ * DD];
__device__ float g_rsum[BH * MM];
__device__ float g_scal[2];

// ---------------- PTX helpers -------------------------------------------------
__device__ __forceinline__ uint32_t elect_one_pred() {
    uint32_t pred;
    asm volatile("{\n\t.reg .pred p;\n\telect.sync _|p, 0xFFFFFFFF;\n\tselp.b32 %0, 1, 0, p;\n\t}"
                 : "=r"(pred));
    return pred;
}
__device__ __forceinline__ uint32_t smem_to_u32(const void* p) {
    uint32_t a;
    asm("{ .reg .u64 t; cvta.to.shared.u64 t, %1; cvt.u32.u64 %0, t; }" : "=r"(a) : "l"(p));
    return a;
}
#define SMEM_SWIZZLE_128B(o) ((o) ^ (((o) >> 3) & 0x70))

static constexpr uint64_t SMEM_DESC_BASE_SW128 =
    (uint64_t(2) << 61) | (uint64_t(1) << 46) | (uint64_t(64) << 32) | (uint64_t(1) << 16);
#define MAKE_SMEM_DESC(base_addr) (SMEM_DESC_BASE_SW128 | ((uint64_t)((base_addr) >> 4) & 0x3FFF))

#define FENCE_PROXY_ASYNC_SHARED_CTA() \
    asm volatile("fence.proxy.async.shared::cta;" ::: "memory")
#define MBARRIER_INIT(a, c) \
    asm volatile("mbarrier.init.shared.b64 [%0], %1;" :: "r"((uint32_t)(a)), "r"((uint32_t)(c)) : "memory")
#define MBARRIER_INVAL(a) \
    asm volatile("mbarrier.inval.shared.b64 [%0];" :: "r"((uint32_t)(a)) : "memory")
#define MBARRIER_WAIT_PARITY(mbar_smem_addr, phase_parity) do { \
    uint32_t _mbar = (uint32_t)(mbar_smem_addr); \
    uint32_t _parity = (uint32_t)(phase_parity); \
    uint32_t _done; \
    asm volatile("{\n\t.reg .pred p;\n\t" \
        "mbarrier.try_wait.parity.acquire.cta.shared::cta.b64 p, [%1], %2;\n\t" \
        "selp.b32 %0, 1, 0, p;\n\t}" \
        : "=r"(_done) : "r"(_mbar), "r"(_parity) : "memory"); \
    if (!_done) { \
        asm volatile("{\n\t.reg .pred P1;\n\t" \
            "WAIT_LOOP_%=:\n\t" \
            "mbarrier.try_wait.parity.acquire.cta.shared::cta.b64 P1, [%0], %1, 0x989680;\n\t" \
            "@P1 bra.uni WAIT_DONE_%=;\n\t" \
            "bra.uni WAIT_LOOP_%=;\n\t" \
            "WAIT_DONE_%=:\n\t}" \
            :: "r"(_mbar), "r"(_parity) : "memory"); \
    } \
} while(0)

#if HAS_TC
#define TCGEN05_ALLOC(smem_result_addr, nCols) \
    asm volatile("tcgen05.alloc.cta_group::1.sync.aligned.shared::cta.b32 [%0], %1;" \
                 :: "r"((uint32_t)(smem_result_addr)), "r"((uint32_t)(nCols)) : "memory")
#define TCGEN05_DEALLOC(tmem_addr, nCols) \
    asm volatile("tcgen05.dealloc.cta_group::1.sync.aligned.b32 %0, %1;" \
                 :: "r"(tmem_addr), "r"((uint32_t)(nCols)))
#define TCGEN05_RELINQUISH_ALLOC_PERMIT() \
    asm volatile("tcgen05.relinquish_alloc_permit.cta_group::1.sync.aligned;")
#define TCGEN05_COMMIT(mbar_smem_addr) \
    asm volatile("tcgen05.commit.cta_group::1.mbarrier::arrive::one.shared::cluster.b64 [%0];" \
                 :: "r"((uint32_t)(mbar_smem_addr)) : "memory")
#define TCGEN05_FENCE_AFTER() \
    asm volatile("tcgen05.fence::after_thread_sync;" ::: "memory")
#define TCGEN05_WAIT_LD() \
    asm volatile("tcgen05.wait::ld.sync.aligned;" ::: "memory")
#define TCGEN05_LD_32X32B_X32(r, tmem_addr) \
    asm volatile("tcgen05.ld.sync.aligned.32x32b.x32.b32 " \
        "{%0, %1, %2, %3, %4, %5, %6, %7, %8, %9, %10, %11, %12, %13, %14, %15, " \
        " %16, %17, %18, %19, %20, %21, %22, %23, %24, %25, %26, %27, %28, %29, %30, %31}, [%32];" \
        : "=r"((r)[0]),  "=r"((r)[1]),  "=r"((r)[2]),  "=r"((r)[3]), \
          "=r"((r)[4]),  "=r"((r)[5]),  "=r"((r)[6]),  "=r"((r)[7]), \
          "=r"((r)[8]),  "=r"((r)[9]),  "=r"((r)[10]), "=r"((r)[11]), \
          "=r"((r)[12]), "=r"((r)[13]), "=r"((r)[14]), "=r"((r)[15]), \
          "=r"((r)[16]), "=r"((r)[17]), "=r"((r)[18]), "=r"((r)[19]), \
          "=r"((r)[20]), "=r"((r)[21]), "=r"((r)[22]), "=r"((r)[23]), \
          "=r"((r)[24]), "=r"((r)[25]), "=r"((r)[26]), "=r"((r)[27]), \
          "=r"((r)[28]), "=r"((r)[29]), "=r"((r)[30]), "=r"((r)[31]) \
        : "r"(tmem_addr))
#define TCGEN05_LD_32X32B_X16(r, tmem_addr) \
    asm volatile("tcgen05.ld.sync.aligned.32x32b.x16.b32 " \
        "{%0, %1, %2, %3, %4, %5, %6, %7, %8, %9, %10, %11, %12, %13, %14, %15}, [%16];" \
        : "=r"((r)[0]),  "=r"((r)[1]),  "=r"((r)[2]),  "=r"((r)[3]), \
          "=r"((r)[4]),  "=r"((r)[5]),  "=r"((r)[6]),  "=r"((r)[7]), \
          "=r"((r)[8]),  "=r"((r)[9]),  "=r"((r)[10]), "=r"((r)[11]), \
          "=r"((r)[12]), "=r"((r)[13]), "=r"((r)[14]), "=r"((r)[15]) \
        : "r"(tmem_addr))

__device__ __forceinline__ void mma_tf32_ss(uint32_t d, uint64_t a, uint64_t b,
                                            uint32_t idesc, uint32_t en) {
    asm volatile("{\n\t.reg .pred p;\n\tsetp.ne.u32 p, %4, 0;\n\t"
                 "tcgen05.mma.cta_group::1.kind::tf32 [%0], %1, %2, %3, p;\n\t}"
                 :: "r"(d), "l"(a), "l"(b), "r"(idesc), "r"(en) : "memory");
}
#endif // HAS_TC

// ---------------- landmarks (also zeroes g_scal) ------------------------------
__global__ void landmarks_k(const float* __restrict__ q, const float* __restrict__ k)
{
    int bh = blockIdx.y, i = blockIdx.x, d = threadIdx.x;
    if (bh == 0 && i == 0 && d < 2) g_scal[d] = 0.f;
    int b = bh >> 3, h = bh & 7;
    float sq = 0.f, sk = 0.f;
    #pragma unroll
    for (int j = 0; j < LL; j++) {
        size_t idx = (((size_t)b * NN_ + (size_t)i * LL + j) * HH + h) * DD + d;
        sq += q[idx];
        sk += k[idx];
    }
    size_t o = ((size_t)bh * MM + i) * DD + d;
    g_QL[o] = sq * (0.125f / (float)LL);
    g_KL[o] = sk * (1.0f  / (float)LL);
}

// ---------------- tcgen05 tf32 batched GEMM (2-stage pipelined, 256 thr) ------
// C = alpha * (A @ B^T) + beta * E;  EXPSUM: C = exp(that), fp32 row sums
// atomically accumulated into Rsum[bh*MM + m].
template<int NT, int KC, bool TRANSB, bool EXPSUM>
__global__ void __launch_bounds__(256)
tcgemm_k(const float* __restrict__ A, size_t a_so, size_t a_si, int lda,
         const float* __restrict__ B, size_t b_so, size_t b_si, int ldb,
         float* __restrict__ C, size_t c_so, size_t c_si, int ldc,
         const float* __restrict__ E, size_t e_so, size_t e_si, int lde,
         float* __restrict__ Rsum,
         int K, int nsplit, size_t c_split, float alpha, float beta)
{
#if HAS_TC
    constexpr int NJ   = KC / 32;
    constexpr int ASZ  = 128 * KC * 4;
    constexpr int BSZ  = NT * KC * 4;
    constexpr int F4R  = KC / 4;

    extern __shared__ char dsm[];
    uint32_t base  = smem_to_u32(dsm);
    uint32_t abase0 = (base + 1023u) & ~1023u;
    uint32_t abase1 = abase0 + ASZ;
    uint32_t bbase0 = abase1 + ASZ;
    uint32_t bbase1 = bbase0 + BSZ;
    uint32_t aux    = bbase1 + BSZ;
    char* dA01[2] = { dsm + (abase0 - base), dsm + (abase1 - base) };
    char* dB01[2] = { dsm + (bbase0 - base), dsm + (bbase1 - base) };
    uint32_t tptr_addr = aux;
    uint32_t mbar0 = aux + 8;
    uint32_t mbar1 = aux + 16;

    int t = threadIdx.x, wid = t >> 5;
    int z = blockIdx.z, bh = z / nsplit, s = z - bh * nsplit;
    int b = bh >> 3, h = bh & 7;
    A += (size_t)b * a_so + (size_t)h * a_si;
    B += (size_t)b * b_so + (size_t)h * b_si;
    C += (size_t)b * c_so + (size_t)h * c_si + (size_t)s * c_split;
    if (E) E += (size_t)b * e_so + (size_t)h * e_si;

    const int m0 = blockIdx.y * 128;
    const int n0 = blockIdx.x * NT;
    const int Kper = K / nsplit;
    const int kb0 = s * Kper;
    const int nchunk = Kper / KC;

    if (wid == 0) TCGEN05_ALLOC(tptr_addr, NT);
    if (t == 0) { MBARRIER_INIT(mbar0, 1); MBARRIER_INIT(mbar1, 1); }
    __syncthreads();
    uint32_t tmem;
    asm volatile("ld.shared.b32 %0, [%1];" : "=r"(tmem) : "r"(tptr_addr));
    if (wid == 0) TCGEN05_RELINQUISH_ALLOC_PERMIT();

    const uint32_t idesc = (1u << 4) | (2u << 7) | (2u << 10) |
                           ((uint32_t)(NT / 8) << 17) | (8u << 24);
    const uint64_t adesc[2] = { MAKE_SMEM_DESC(abase0), MAKE_SMEM_DESC(abase1) };
    const uint64_t bdesc[2] = { MAKE_SMEM_DESC(bbase0), MAKE_SMEM_DESC(bbase1) };

    int ph0 = 0, ph1 = 0;
    for (int c = 0; c < nchunk; c++) {
        const int st = c & 1;
        if (c >= 2) {
            if (st) { MBARRIER_WAIT_PARITY(mbar1, ph1); ph1 ^= 1; }
            else    { MBARRIER_WAIT_PARITY(mbar0, ph0); ph0 ^= 1; }
        }
        char* dA = dA01[st];
        char* dB = dB01[st];
        const int kb = kb0 + c * KC;
        #pragma unroll
        for (int p = 0; p < (128 * F4R) / 256; p++) {
            int idx = t + p * 256;
            int r = idx / F4R, f = idx % F4R;
            int j = f >> 3, fj = f & 7;
            float4 v4 = *(const float4*)(A + (size_t)(m0 + r) * lda + kb + f * 4);
            *(float4*)(dA + j * 16384 + SMEM_SWIZZLE_128B((uint32_t)(r * 128 + fj * 16))) = v4;
        }
        if (!TRANSB) {
            #pragma unroll
            for (int p = 0; p < (NT * F4R) / 256; p++) {
                int idx = t + p * 256;
                int r = idx / F4R, f = idx % F4R;
                int j = f >> 3, fj = f & 7;
                float4 v4 = *(const float4*)(B + (size_t)(n0 + r) * ldb + kb + f * 4);
                *(float4*)(dB + j * (NT * 128) + SMEM_SWIZZLE_128B((uint32_t)(r * 128 + fj * 16))) = v4;
            }
        } else {
            constexpr int NF = NT / 4;
            #pragma unroll
            for (int p = 0; p < (KC * NF) / 256; p++) {
                int idx = t + p * 256;
                int kk = idx / NF, nf = idx - kk * NF;
                int j = kk >> 5, kkin = kk & 31;
                float4 v4 = *(const float4*)(B + (size_t)(kb + kk) * ldb + n0 + nf * 4);
                int nb = nf * 4;
                char* db = dB + j * (NT * 128);
                *(float*)(db + SMEM_SWIZZLE_128B((uint32_t)((nb + 0) * 128 + kkin * 4))) = v4.x;
                *(float*)(db + SMEM_SWIZZLE_128B((uint32_t)((nb + 1) * 128 + kkin * 4))) = v4.y;
                *(float*)(db + SMEM_SWIZZLE_128B((uint32_t)((nb + 2) * 128 + kkin * 4))) = v4.z;
                *(float*)(db + SMEM_SWIZZLE_128B((uint32_t)((nb + 3) * 128 + kkin * 4))) = v4.w;
            }
        }
        FENCE_PROXY_ASYNC_SHARED_CTA();
        __syncthreads();
        if (wid == 0) {
            if (elect_one_pred()) {
                #pragma unroll
                for (int j = 0; j < NJ; j++)
                    #pragma unroll
                    for (int ss = 0; ss < 4; ss++)
                        mma_tf32_ss(tmem, adesc[st] + j * 1024 + ss * 2,
                                    bdesc[st] + j * (NT * 8) + ss * 2, idesc,
                                    (c > 0 || j > 0 || ss > 0) ? 1u : 0u);
                TCGEN05_COMMIT(st ? mbar1 : mbar0);
            }
        }
    }
    if ((nchunk - 1) & 1) { MBARRIER_WAIT_PARITY(mbar1, ph1); }
    else                  { MBARRIER_WAIT_PARITY(mbar0, ph0); }

    TCGEN05_FENCE_AFTER();
    const int lid = t & 31;
    const int m = m0 + (wid & 3) * 32 + lid;
    const int half = wid >> 2;
    float lsum = 0.f;
    #pragma unroll
    for (int cb = half * (NT / 2); cb < (half + 1) * (NT / 2); cb += 32) {
        uint32_t r[32];
        TCGEN05_LD_32X32B_X32(r, tmem + cb);
        TCGEN05_WAIT_LD();
        float* crow = C + (size_t)m * ldc + (n0 + cb);
        const float* erow = E ? (E + (size_t)m * lde + (n0 + cb)) : (const float*)0;
        #pragma unroll
        for (int j = 0; j < 32; j += 4) {
            float4 o;
            o.x = alpha * __uint_as_float(r[j + 0]);
            o.y = alpha * __uint_as_float(r[j + 1]);
            o.z = alpha * __uint_as_float(r[j + 2]);
            o.w = alpha * __uint_as_float(r[j + 3]);
            if (erow) {
                float4 e4 = *(const float4*)(erow + j);
                o.x += beta * e4.x; o.y += beta * e4.y;
                o.z += beta * e4.z; o.w += beta * e4.w;
            }
            if (EXPSUM) {
                o.x = __expf(o.x); o.y = __expf(o.y);
                o.z = __expf(o.z); o.w = __expf(o.w);
                lsum += (o.x + o.y) + (o.z + o.w);
            }
            *(float4*)(crow + j) = o;
        }
    }
    if (EXPSUM) atomicAdd(Rsum + (size_t)bh * MM + m, lsum);
    __syncthreads();
    if (t == 0) { MBARRIER_INVAL(mbar0); MBARRIER_INVAL(mbar1); }
    __syncthreads();
    if (wid == 0) TCGEN05_DEALLOC(tmem, NT);
#else
    __trap();
#endif
}

// ---------------- fused attn1 softmax + OA GEMM (256 threads) -----------------
// OA[m,:] = softmax(0.125 q KL^T) @ W.  No max pass (shift-invariant, scores
// small). TMEM 512, D1 = tmem+256 (NO aliasing). 8 warps: P-loop splits each
// 32-col chunk between warp halves (warps 4-7 address the same TMEM
// subpartitions as 0-3 -- pattern verified in the tcgemm 8-warp epilogue).
__global__ void __launch_bounds__(256)
fused_attn1_k(const float* __restrict__ q)
{
#if HAS_TC
    extern __shared__ char dsm[];
    uint32_t base  = smem_to_u32(dsm);
    uint32_t a0 = (base + 1023u) & ~1023u;
    uint32_t a1 = a0 + 16384;
    uint32_t b0 = a1 + 16384;
    uint32_t b1 = b0 + 32768;
    uint32_t wb = b1 + 32768;
    uint32_t p0 = wb + 65536;
    uint32_t p1 = p0 + 16384;
    uint32_t aux = p1 + 16384;
    char* dA[2] = { dsm + (a0 - base), dsm + (a1 - base) };
    char* dB[2] = { dsm + (b0 - base), dsm + (b1 - base) };
    char* dW    = dsm + (wb - base);
    char* dP[2] = { dsm + (p0 - base), dsm + (p1 - base) };
    uint32_t tptr = aux, sbar = aux + 8, pm0 = aux + 16, pm1 = aux + 24;
    float* redsum = (float*)(dsm + (aux + 32 - base));   // 128 floats

    const int t = threadIdx.x, wid = t >> 5, lid = t & 31;
    const int bh = blockIdx.y, b = bh >> 3, h = bh & 7;
    const int m0 = blockIdx.x * 128;
    const float* qb = q + (size_t)b * ((size_t)NN_ * HH * DD) + (size_t)h * DD;
    const float* KLb = g_KL + (size_t)bh * MM * DD;
    const float* Wb  = g_W  + (size_t)bh * MM * DD;
    float* OAb = g_OA + (size_t)bh * NN_ * DD;

    if (wid == 0) TCGEN05_ALLOC(tptr, 512);
    if (t == 0) { MBARRIER_INIT(sbar, 1); MBARRIER_INIT(pm0, 1); MBARRIER_INIT(pm1, 1); }
    __syncthreads();
    uint32_t tmem;
    asm volatile("ld.shared.b32 %0, [%1];" : "=r"(tmem) : "r"(tptr));
    if (wid == 0) TCGEN05_RELINQUISH_ALLOC_PERMIT();
    const uint32_t D1 = tmem + 256;

    // ---- loads: 256 threads ----
    #pragma unroll
    for (int kc = 0; kc < 2; kc++) {
        #pragma unroll
        for (int p = 0; p < 4; p++) {
            int idx = t + p * 256;
            int r = idx >> 3, f = idx & 7;
            float4 v4 = *(const float4*)(qb + (size_t)(m0 + r) * (HH * DD) + kc * 32 + f * 4);
            *(float4*)(dA[kc] + SMEM_SWIZZLE_128B((uint32_t)(r * 128 + f * 16))) = v4;
        }
        #pragma unroll
        for (int p = 0; p < 8; p++) {
            int idx = t + p * 256;
            int r = idx >> 3, f = idx & 7;
            float4 v4 = *(const float4*)(KLb + (size_t)r * DD + kc * 32 + f * 4);
            *(float4*)(dB[kc] + SMEM_SWIZZLE_128B((uint32_t)(r * 128 + f * 16))) = v4;
        }
    }
    #pragma unroll
    for (int cb = 0; cb < 8; cb++) {
        #pragma unroll
        for (int p = 0; p < 2; p++) {
            int idx = t + p * 256;
            int kk = idx >> 4, nf = idx & 15;
            float4 v4 = *(const float4*)(Wb + (size_t)(cb * 32 + kk) * DD + nf * 4);
            int nb = nf * 4;
            char* wchunk = dW + cb * 8192;
            *(float*)(wchunk + SMEM_SWIZZLE_128B((uint32_t)((nb + 0) * 128 + kk * 4))) = v4.x;
            *(float*)(wchunk + SMEM_SWIZZLE_128B((uint32_t)((nb + 1) * 128 + kk * 4))) = v4.y;
            *(float*)(wchunk + SMEM_SWIZZLE_128B((uint32_t)((nb + 2) * 128 + kk * 4))) = v4.z;
            *(float*)(wchunk + SMEM_SWIZZLE_128B((uint32_t)((nb + 3) * 128 + kk * 4))) = v4.w;
        }
    }
    FENCE_PROXY_ASYNC_SHARED_CTA();
    __syncthreads();

    // ---- score phase ----
    const uint32_t idesc_s  = (1u << 4) | (2u << 7) | (2u << 10) | (32u << 17) | (8u << 24);
    const uint32_t idesc_oa = (1u << 4) | (2u << 7) | (2u << 10) | (8u  << 17) | (8u << 24);
    if (wid == 0) {
        if (elect_one_pred()) {
            #pragma unroll
            for (int kc = 0; kc < 2; kc++) {
                uint64_t ad = MAKE_SMEM_DESC(kc ? a1 : a0);
                uint64_t bdd = MAKE_SMEM_DESC(kc ? b1 : b0);
                #pragma unroll
                for (int ss = 0; ss < 4; ss++)
                    mma_tf32_ss(tmem, ad + ss * 2, bdd + ss * 2, idesc_s,
                                (kc > 0 || ss > 0) ? 1u : 0u);
            }
            TCGEN05_COMMIT(sbar);
        }
    }
    MBARRIER_WAIT_PARITY(sbar, 0);
    TCGEN05_FENCE_AFTER();

    // ---- P loop: each chunk's 32 cols split between warp halves ----
    const int prow = (wid & 3) * 32 + lid;       // this thread's tile row
    const int chalf = (wid >> 2) * 16;           // column half within chunk
    float psum = 0.f;
    int php0 = 0, php1 = 0;
    const uint64_t pdesc[2] = { MAKE_SMEM_DESC(p0), MAKE_SMEM_DESC(p1) };
    const uint64_t wdesc0 = MAKE_SMEM_DESC(wb);
    for (int cb = 0; cb < 8; cb++) {
        const int st = cb & 1;
        if (cb >= 2) {
            if (st) { MBARRIER_WAIT_PARITY(pm1, php1); php1 ^= 1; }
            else    { MBARRIER_WAIT_PARITY(pm0, php0); php0 ^= 1; }
        }
        uint32_t r[16];
        TCGEN05_LD_32X32B_X16(r, tmem + cb * 32 + chalf);
        TCGEN05_WAIT_LD();
        float e[16];
        #pragma unroll
        for (int j = 0; j < 16; j++) {
            e[j] = __expf(0.125f * __uint_as_float(r[j]));
            psum += e[j];
        }
        char* P = dP[st];
        #pragma unroll
        for (int g = 0; g < 4; g++) {
            float4 v4 = make_float4(e[g*4], e[g*4+1], e[g*4+2], e[g*4+3]);
            *(float4*)(P + SMEM_SWIZZLE_128B((uint32_t)(prow * 128 + chalf * 4 + g * 16))) = v4;
        }
        FENCE_PROXY_ASYNC_SHARED_CTA();
        __syncthreads();
        if (wid == 0) {
            if (elect_one_pred()) {
                #pragma unroll
                for (int ss = 0; ss < 4; ss++)
                    mma_tf32_ss(D1, pdesc[st] + ss * 2, wdesc0 + cb * 512 + ss * 2,
                                idesc_oa, (cb > 0 || ss > 0) ? 1u : 0u);
                TCGEN05_COMMIT(st ? pm1 : pm0);
            }
        }
    }
    // combine the two column-half partial sums per row
    if (wid < 4) redsum[prow] = psum;
    __syncthreads();
    if (wid >= 4) redsum[prow] += psum;
    __syncthreads();
    const float sum = redsum[prow];

    MBARRIER_WAIT_PARITY(pm1, php1);
    TCGEN05_FENCE_AFTER();

    // ---- epilogue: warps 0-3 write D1 cols [0,32), warps 4-7 cols [32,64) ----
    const float inv = 1.0f / sum;
    const int ecol = (wid >> 2) * 32;
    {
        uint32_t r[32];
        TCGEN05_LD_32X32B_X32(r, D1 + ecol);
        TCGEN05_WAIT_LD();
        float* orow = OAb + (size_t)(m0 + prow) * DD + ecol;
        #pragma unroll
        for (int j = 0; j < 32; j += 4) {
            float4 o;
            o.x = inv * __uint_as_float(r[j + 0]);
            o.y = inv * __uint_as_float(r[j + 1]);
            o.z = inv * __uint_as_float(r[j + 2]);
            o.w = inv * __uint_as_float(r[j + 3]);
            *(float4*)(orow + j) = o;
        }
    }
    __syncthreads();
    if (t == 0) { MBARRIER_INVAL(sbar); MBARRIER_INVAL(pm0); MBARRIER_INVAL(pm1); }
    __syncthreads();
    if (wid == 0) TCGEN05_DEALLOC(tmem, 512);
#else
    __trap();
#endif
}

// ---------------- register-resident row softmax (attn2 only) ------------------
template<int C>
__global__ void softmax_reg_k(float* __restrict__ X)
{
    constexpr int V = C / 256;
    float* row = X + (size_t)blockIdx.x * C;
    int t = threadIdx.x;
    float v[V];
    float mx = -1e30f;
    #pragma unroll
    for (int i = 0; i < V; i++) { v[i] = row[t + i * 256]; mx = fmaxf(mx, v[i]); }
    __shared__ float red[256];
    red[t] = mx; __syncthreads();
    for (int s = 128; s > 0; s >>= 1) { if (t < s) red[t] = fmaxf(red[t], red[t + s]); __syncthreads(); }
    mx = red[0]; __syncthreads();
    float sum = 0.f;
    #pragma unroll
    for (int i = 0; i < V; i++) { v[i] = __expf(v[i] - mx); sum += v[i]; }
    red[t] = sum; __syncthreads();
    for (int s = 128; s > 0; s >>= 1) { if (t < s) red[t] += red[t + s]; __syncthreads(); }
    float inv = 1.0f / red[0];
    #pragma unroll
    for (int i = 0; i < V; i++) row[t + i * 256] = v[i] * inv;
}

// ---------------- pinv init ---------------------------------------------------
__global__ void __launch_bounds__(1024) colmax_k(const float* __restrict__ X)
{
    int bh = blockIdx.x, t = threadIdx.x;
    int col = t & 255, part = t >> 8;
    const float* xb = X + (size_t)bh * MM * MM;
    float cs = 0.f;
    #pragma unroll 8
    for (int i = part * 64; i < part * 64 + 64; i++) cs += xb[(size_t)i * MM + col];
    __shared__ float sm[1024];
    sm[t] = cs; __syncthreads();
    if (t < 256) sm[t] = (sm[t] + sm[t + 256]) + (sm[t + 512] + sm[t + 768]);
    __syncthreads();
    for (int s = 128; s > 0; s >>= 1) {
        if (t < s) sm[t] = fmaxf(sm[t], sm[t + s]);
        __syncthreads();
    }
    if (t == 0) atomicMax((int*)&g_scal[0], __float_as_int(sm[0]));
}

__global__ void z0_k(const float* __restrict__ X, float* __restrict__ Z)
{
    __shared__ float tile[32][33];
    int bh = blockIdx.z;
    const float* xb = X + (size_t)bh * MM * MM;
    float* zb = Z + (size_t)bh * MM * MM;
    int i0 = blockIdx.x * 32, j0 = blockIdx.y * 32;
    tile[threadIdx.y][threadIdx.x] = xb[(size_t)(j0 + threadIdx.y) * MM + (i0 + threadIdx.x)];
    __syncthreads();
    float inv = 1.0f / g_scal[0];
    zb[(size_t)(i0 + threadIdx.y) * MM + (j0 + threadIdx.x)] = tile[threadIdx.x][threadIdx.y] * inv;
}

// ---------------- K-split reduce for G + softmax normalization ----------------
__global__ void reduce_g_k(const float* __restrict__ Gp, float* __restrict__ G)
{
    int i = blockIdx.x * 256 + threadIdx.x;
    const size_t stride = (size_t)BH * MM * DD;
    float s = 0.f;
    #pragma unroll
    for (int p = 0; p < GSPLIT; p++) s += Gp[(size_t)p * stride + i];
    G[i] = s / g_rsum[i >> 6];
}

// ---------------- epilogue: depthwise conv + residual + transpose ------------
__global__ void epilogue_k(const float* __restrict__ v, const float* __restrict__ rw,
                           const float* __restrict__ OA, float* __restrict__ out)
{
    __shared__ float vt[96 * 64];
    __shared__ float w[KERN];
    int bh = blockIdx.y, b = bh >> 3, h = bh & 7;
    int i0 = blockIdx.x * 64;
    int t = threadIdx.x;
    if (t < KERN) w[t] = rw[h * KERN + t];
    #pragma unroll
    for (int p = 0; p < 6; p++) {
        int idx = t + p * 256;
        int r = idx >> 4, f = idx & 15;
        int ii = i0 - 16 + r;
        float4 val = make_float4(0.f, 0.f, 0.f, 0.f);
        if (ii >= 0 && ii < NN_)
            val = *(const float4*)(v + (((size_t)b * NN_ + ii) * HH + h) * DD + f * 4);
        *(float4*)(vt + r * 64 + f * 4) = val;
    }
    __syncthreads();
    int d4 = (t & 15) * 4;
    int irow = t >> 4;
    #pragma unroll
    for (int rr = 0; rr < 4; rr++) {
        int il = irow + rr * 16;
        int i = i0 + il;
        float4 acc = *(const float4*)(OA + ((size_t)bh * NN_ + i) * DD + d4);
        #pragma unroll
        for (int tap = 0; tap < KERN; tap++) {
            float4 vv = *(const float4*)(vt + (il + tap) * 64 + d4);
            float wt = w[tap];
            acc.x += vv.x * wt; acc.y += vv.y * wt;
            acc.z += vv.z * wt; acc.w += vv.w * wt;
        }
        *(float4*)(out + (((size_t)b * NN_ + i) * HH + h) * DD + d4) = acc;
    }
}

// ---------------- host side ---------------------------------------------------
static size_t shm_gemm(int NT, int KC) {
    return 1024 + 2 * (size_t)(128 * KC * 4) + 2 * (size_t)(NT * KC * 4) + 64;
}
static const size_t SHM_FUSED = 1024 + 2 * 16384 + 2 * 32768 + 65536 + 2 * 16384 + 64 + 512;

extern "C" void kernel_launch(void* const* d_in, const int* in_sizes, int n_in,
                              void* d_out, int out_size)
{
    const float* q  = (const float*)d_in[0];
    const float* k  = (const float*)d_in[1];
    const float* v  = (const float*)d_in[2];
    const float* rw = (const float*)d_in[3];
    float* out = (float*)d_out;

    static bool attrs_set = false;
    if (!attrs_set) {
        cudaFuncSetAttribute(tcgemm_k<128, 64, true,  false>, cudaFuncAttributeMaxDynamicSharedMemorySize, (int)shm_gemm(128, 64));
        cudaFuncSetAttribute(tcgemm_k<128, 32, false, false>, cudaFuncAttributeMaxDynamicSharedMemorySize, (int)shm_gemm(128, 32));
        cudaFuncSetAttribute(tcgemm_k<128, 32, false, true >, cudaFuncAttributeMaxDynamicSharedMemorySize, (int)shm_gemm(128, 32));
        cudaFuncSetAttribute(tcgemm_k<64,  32, true,  false>, cudaFuncAttributeMaxDynamicSharedMemorySize, (int)shm_gemm(64, 32));
        cudaFuncSetAttribute(tcgemm_k<64,  64, true,  false>, cudaFuncAttributeMaxDynamicSharedMemorySize, (int)shm_gemm(64, 64));
        cudaFuncSetAttribute(fused_attn1_k, cudaFuncAttributeMaxDynamicSharedMemorySize, (int)SHM_FUSED);
        attrs_set = true;
    }

    float *QL, *KL, *X, *ZA, *ZB, *XZ, *T2, *T3, *S, *G, *Gp, *W, *OA, *RS;
    cudaGetSymbolAddress((void**)&QL, g_QL);
    cudaGetSymbolAddress((void**)&KL, g_KL);
    cudaGetSymbolAddress((void**)&X,  g_X);
    cudaGetSymbolAddress((void**)&ZA, g_ZA);
    cudaGetSymbolAddress((void**)&ZB, g_ZB);
    cudaGetSymbolAddress((void**)&XZ, g_XZ);
    cudaGetSymbolAddress((void**)&T2, g_T2);
    cudaGetSymbolAddress((void**)&T3, g_T3);
    cudaGetSymbolAddress((void**)&S,  g_S);
    cudaGetSymbolAddress((void**)&G,  g_G);
    cudaGetSymbolAddress((void**)&Gp, g_Gp);
    cudaGetSymbolAddress((void**)&W,  g_W);
    cudaGetSymbolAddress((void**)&OA, g_OA);
    cudaGetSymbolAddress((void**)&RS, g_rsum);

    const size_t LB  = (size_t)MM * DD;
    const size_t XB  = (size_t)MM * MM;
    const size_t SB  = (size_t)NN_ * MM;
    const size_t QSO = (size_t)NN_ * HH * DD;
    const size_t QSI = DD;
    const int    QLD = HH * DD;

    // 0: landmarks (zeroes g_scal); rsum zeroed async
    landmarks_k<<<dim3(MM, BH), DD>>>(q, k);
    cudaMemsetAsync(RS, 0, BH * MM * sizeof(float));

    // 1: attn2 scores X = QL @ KL^T
    tcgemm_k<128, 32, false, false><<<dim3(2, 2, BH), 256, shm_gemm(128, 32)>>>(
        QL, 8*LB, LB, DD,  KL, 8*LB, LB, DD,  X, 8*XB, XB, MM,
        nullptr, 0, 0, 0,  nullptr,  DD, 1, 0, 1.0f, 0.0f);
    // 2: softmax rows
    softmax_reg_k<MM><<<BH * MM, 256>>>(X);
    // 3: column-sum max
    colmax_k<<<BH, 1024>>>(X);
    // 4: z0 = X^T * inv
    z0_k<<<dim3(MM/32, MM/32, BH), dim3(32, 32)>>>(X, ZA);

    // 5..28: Newton-Schulz (KC=64)
    for (int it = 0; it < 6; it++) {
        float* zc = (it & 1) ? ZB : ZA;
        float* zn = (it & 1) ? ZA : ZB;
        tcgemm_k<128, 64, true, false><<<dim3(2, 2, BH), 256, shm_gemm(128, 64)>>>(
            X,  8*XB, XB, MM,  zc, 8*XB, XB, MM,  XZ, 8*XB, XB, MM,
            nullptr, 0, 0, 0,  nullptr,  MM, 1, 0, 1.0f, 0.0f);
        tcgemm_k<128, 64, true, false><<<dim3(2, 2, BH), 256, shm_gemm(128, 64)>>>(
            XZ, 8*XB, XB, MM,  XZ, 8*XB, XB, MM,  T2, 8*XB, XB, MM,
            XZ, 8*XB, XB, MM,  nullptr,  MM, 1, 0, -1.0f, 7.0f);
        tcgemm_k<128, 64, true, false><<<dim3(2, 2, BH), 256, shm_gemm(128, 64)>>>(
            XZ, 8*XB, XB, MM,  T2, 8*XB, XB, MM,  T3, 8*XB, XB, MM,
            XZ, 8*XB, XB, MM,  nullptr,  MM, 1, 0, -1.0f, 15.0f);
        tcgemm_k<128, 64, true, false><<<dim3(2, 2, BH), 256, shm_gemm(128, 64)>>>(
            zc, 8*XB, XB, MM,  T3, 8*XB, XB, MM,  zn, 8*XB, XB, MM,
            zc, 8*XB, XB, MM,  nullptr,  MM, 1, 0, -0.25f, 3.25f);
    }
    // final z in ZA

    // attn3: S = exp(QL @ k^T), fp32 row sums into g_rsum
    tcgemm_k<128, 32, false, true><<<dim3(NN_/128, 2, BH), 256, shm_gemm(128, 32)>>>(
        QL, 8*LB, LB, DD,  k, QSO, QSI, QLD,  S, 8*SB, SB, NN_,
        nullptr, 0, 0, 0,  RS,  DD, 1, 0, 1.0f, 0.0f);

    // G = (S @ v) / rsum  (K-split x8; division in reduce)
    tcgemm_k<64, 32, true, false><<<dim3(1, 2, BH * GSPLIT), 256, shm_gemm(64, 32)>>>(
        S, 8*SB, SB, NN_,  v, QSO, QSI, QLD,  Gp, 8*LB, LB, DD,
        nullptr, 0, 0, 0,  nullptr,  NN_, GSPLIT, (size_t)BH * LB, 1.0f, 0.0f);
    reduce_g_k<<<(BH * MM * DD) / 256, 256>>>(Gp, G);

    // W = ZA @ G  (KC=64)
    tcgemm_k<64, 64, true, false><<<dim3(1, 2, BH), 256, shm_gemm(64, 64)>>>(
        ZA, 8*XB, XB, MM,  G, 8*LB, LB, DD,  W, 8*LB, LB, DD,
        nullptr, 0, 0, 0,  nullptr,  MM, 1, 0, 1.0f, 0.0f);

    // fused attn1 softmax + OA (256 threads)
    fused_attn1_k<<<dim3(NN_ / 128, BH), 256, SHM_FUSED>>>(q);

    // depthwise conv residual + transpose
    epilogue_k<<<dim3(NN_ / 64, BH), 256>>>(v, rw, OA, out);
}